// round 4
// baseline (speedup 1.0000x reference)
#include <cuda_runtime.h>

#define LSEQ 2048
#define BATCH 2
#define HID 1024
#define NHEAD 16
#define DH 64
#define PREL 50
#define NR 101            // 2P+1
#define NROWS (LSEQ*BATCH)  // 4096
#define PAD 68

// Scratch (static device globals -- no runtime allocation)
__device__ float g_Q[NROWS * HID];
__device__ float g_K[NROWS * HID];
__device__ float g_V[NROWS * HID];
__device__ float g_O[NROWS * HID];

// ---------------------------------------------------------------------------
// GEMM: C[M,N] = A[M,K] * W[N,K]^T + bias[N]
// 64x64 block tile, 16-deep k panels, 4x4 register microtile, 256 threads.
// mode selects scratch src/dst so host never needs device symbol addresses:
//   mode 0: A=ext, C=g_Q ; 1: A=ext, C=g_K ; 2: A=ext, C=g_V ; 3: A=g_O, C=ext
// ---------------------------------------------------------------------------
__global__ __launch_bounds__(256) void gemm_bias(
    const float* __restrict__ A_ext, const float* __restrict__ W,
    const float* __restrict__ bias, float* __restrict__ C_ext, int mode)
{
    const float* A = (mode == 3) ? g_O : A_ext;
    float* C = (mode == 0) ? g_Q : (mode == 1) ? g_K : (mode == 2) ? g_V : C_ext;
    const int K = HID, N = HID;

    __shared__ float As[16][PAD];
    __shared__ float Ws[16][PAD];

    const int tid = threadIdx.x;
    const int tx = tid & 15, ty = tid >> 4;
    const int rowBase = blockIdx.y * 64;
    const int colBase = blockIdx.x * 64;
    const int lr = tid >> 2;          // 0..63
    const int lc = (tid & 3) * 4;     // 0,4,8,12
    const float* Aload = A + (size_t)(rowBase + lr) * K + lc;
    const float* Wload = W + (size_t)(colBase + lr) * K + lc;

    float acc[4][4] = {};

    for (int k0 = 0; k0 < K; k0 += 16) {
        float4 a4 = *reinterpret_cast<const float4*>(Aload + k0);
        float4 w4 = *reinterpret_cast<const float4*>(Wload + k0);
        As[lc + 0][lr] = a4.x; As[lc + 1][lr] = a4.y;
        As[lc + 2][lr] = a4.z; As[lc + 3][lr] = a4.w;
        Ws[lc + 0][lr] = w4.x; Ws[lc + 1][lr] = w4.y;
        Ws[lc + 2][lr] = w4.z; Ws[lc + 3][lr] = w4.w;
        __syncthreads();
        #pragma unroll
        for (int kk = 0; kk < 16; kk++) {
            float4 ra = *reinterpret_cast<const float4*>(&As[kk][ty * 4]);
            float4 rb = *reinterpret_cast<const float4*>(&Ws[kk][tx * 4]);
            float a[4] = {ra.x, ra.y, ra.z, ra.w};
            float w[4] = {rb.x, rb.y, rb.z, rb.w};
            #pragma unroll
            for (int i = 0; i < 4; i++)
                #pragma unroll
                for (int j = 0; j < 4; j++)
                    acc[i][j] += a[i] * w[j];
        }
        __syncthreads();
    }

    #pragma unroll
    for (int i = 0; i < 4; i++) {
        int row = rowBase + ty * 4 + i;
        #pragma unroll
        for (int j = 0; j < 4; j++) {
            int col = colBase + tx * 4 + j;
            C[(size_t)row * N + col] = acc[i][j] + bias[col];
        }
    }
}

// ---------------------------------------------------------------------------
// Fused relative-position attention.
// Grid: (q_tiles=32, heads=16, batch=2). Block: 256 threads, q-tile = 64.
// Streams K/V tiles of 64. Unnormalized streaming softmax (logits are tiny:
// ~N(0,0.41), no max subtraction needed).
//   S2[q][r]   = Q[q] . rel_k[r]                       (101 buckets)
//   logits     = (Q K^T + S2[q][clip(k-q)]) / 8
//   T[q][r]    = sum of p over k in bucket r  -> w2 = T @ rel_v
//   out        = (sum p*v + w2) / sum p
// ---------------------------------------------------------------------------
__global__ __launch_bounds__(256) void attn_kernel(
    const float* __restrict__ relk, const float* __restrict__ relv)
{
    extern __shared__ float sm[];
    float* QsT = sm;                    // [64 d][PAD] transposed
    float* KsT = QsT + 64 * PAD;        // [64 d][PAD] transposed
    float* Vs  = KsT + 64 * PAD;        // [64 k][PAD] row-major
    float* Ps  = Vs  + 64 * PAD;        // [64 q][PAD]
    float* S2  = Ps  + 64 * PAD;        // [64 q][NR]
    float* Tm  = S2  + 64 * NR;         // [64 q][NR]
    float* den = Tm  + 64 * NR;         // [64]

    const int tid = threadIdx.x;
    const int tx = tid & 15, ty = tid >> 4;
    const int qt = blockIdx.x, h = blockIdx.y, b = blockIdx.z;
    const int q0 = qt * 64;
    const int headOff = h * DH;

    // Load Q tile transposed: QsT[d][q]
    #pragma unroll
    for (int m = 0; m < 4; m++) {
        int idx = tid + m * 256;
        int row = idx >> 4;
        int c4 = (idx & 15) * 4;
        const float* gp = g_Q + ((size_t)(q0 + row) * BATCH + b) * HID + headOff + c4;
        float4 v = *reinterpret_cast<const float4*>(gp);
        QsT[(c4 + 0) * PAD + row] = v.x;
        QsT[(c4 + 1) * PAD + row] = v.y;
        QsT[(c4 + 2) * PAD + row] = v.z;
        QsT[(c4 + 3) * PAD + row] = v.w;
    }
    for (int o = tid; o < 64 * NR; o += 256) Tm[o] = 0.0f;
    if (tid < 64) den[tid] = 0.0f;
    __syncthreads();

    // S2[q][r] = sum_d Q[q][d] * rel_k[r][d]
    for (int o = tid; o < 64 * NR; o += 256) {
        int q = o / NR, r = o - q * NR;
        float s = 0.0f;
        #pragma unroll 16
        for (int d = 0; d < 64; d++)
            s += QsT[d * PAD + q] * __ldg(&relk[r * DH + d]);
        S2[o] = s;
    }

    float acc[4][4] = {};
    const float inv_scale = 0.125f;   // 1/sqrt(64)

    for (int kt = 0; kt < LSEQ / 64; kt++) {
        __syncthreads();  // protect K/V/Ps reuse across iterations (also covers S2 init)
        const int k0 = kt * 64;

        // Load K (transposed) and V (row-major) tiles
        #pragma unroll
        for (int m = 0; m < 4; m++) {
            int idx = tid + m * 256;
            int row = idx >> 4;
            int c4 = (idx & 15) * 4;
            const float* gk = g_K + ((size_t)(k0 + row) * BATCH + b) * HID + headOff + c4;
            float4 v = *reinterpret_cast<const float4*>(gk);
            KsT[(c4 + 0) * PAD + row] = v.x;
            KsT[(c4 + 1) * PAD + row] = v.y;
            KsT[(c4 + 2) * PAD + row] = v.z;
            KsT[(c4 + 3) * PAD + row] = v.w;
            const float* gv = g_V + ((size_t)(k0 + row) * BATCH + b) * HID + headOff + c4;
            *reinterpret_cast<float4*>(&Vs[row * PAD + c4]) =
                *reinterpret_cast<const float4*>(gv);
        }
        __syncthreads();

        // S = Q K^T  (4x4 microtile per thread)
        float s[4][4] = {};
        #pragma unroll 8
        for (int d = 0; d < 64; d++) {
            float4 ra = *reinterpret_cast<const float4*>(&QsT[d * PAD + ty * 4]);
            float4 rb = *reinterpret_cast<const float4*>(&KsT[d * PAD + tx * 4]);
            float a[4] = {ra.x, ra.y, ra.z, ra.w};
            float bb[4] = {rb.x, rb.y, rb.z, rb.w};
            #pragma unroll
            for (int i = 0; i < 4; i++)
                #pragma unroll
                for (int j = 0; j < 4; j++)
                    s[i][j] += a[i] * bb[j];
        }

        // Fast path: tile fully clipped (most tiles, since L >> P)
        int rel_const = -1;
        if (k0 - (q0 + 63) >= PREL)      rel_const = 2 * PREL;  // k - q >= P everywhere
        else if (q0 - (k0 + 63) >= PREL) rel_const = 0;         // q - k >= P everywhere

        #pragma unroll
        for (int i = 0; i < 4; i++) {
            const int ql = ty * 4 + i;
            const int qg = q0 + ql;
            float rowsum = 0.0f;
            if (rel_const >= 0) {
                const float s2v = S2[ql * NR + rel_const];
                #pragma unroll
                for (int j = 0; j < 4; j++) {
                    float p = __expf((s[i][j] + s2v) * inv_scale);
                    Ps[ql * PAD + tx * 4 + j] = p;
                    rowsum += p;
                }
                atomicAdd(&Tm[ql * NR + rel_const], rowsum);
            } else {
                #pragma unroll
                for (int j = 0; j < 4; j++) {
                    int kg = k0 + tx * 4 + j;
                    int rel = kg - qg;
                    rel = min(max(rel, -PREL), PREL) + PREL;
                    float p = __expf((s[i][j] + S2[ql * NR + rel]) * inv_scale);
                    Ps[ql * PAD + tx * 4 + j] = p;
                    rowsum += p;
                    atomicAdd(&Tm[ql * NR + rel], p);
                }
            }
            atomicAdd(&den[ql], rowsum);
        }
        __syncthreads();

        // O += P V
        #pragma unroll 8
        for (int k = 0; k < 64; k++) {
            float pa[4];
            #pragma unroll
            for (int i = 0; i < 4; i++) pa[i] = Ps[(ty * 4 + i) * PAD + k];
            float4 vb = *reinterpret_cast<const float4*>(&Vs[k * PAD + tx * 4]);
            float vv[4] = {vb.x, vb.y, vb.z, vb.w};
            #pragma unroll
            for (int i = 0; i < 4; i++)
                #pragma unroll
                for (int j = 0; j < 4; j++)
                    acc[i][j] += pa[i] * vv[j];
        }
    }
    __syncthreads();  // T, den complete

    // w2 = T @ rel_v ; normalize ; store per-head output
    #pragma unroll
    for (int i = 0; i < 4; i++) {
        const int ql = ty * 4 + i;
        float w2[4] = {0.f, 0.f, 0.f, 0.f};
        for (int r = 0; r < NR; r++) {
            float t = Tm[ql * NR + r];
            #pragma unroll
            for (int j = 0; j < 4; j++)
                w2[j] += t * __ldg(&relv[r * DH + tx * 4 + j]);
        }
        const float invden = 1.0f / den[ql];
        const int lg = q0 + ql;
        float* op = g_O + ((size_t)lg * BATCH + b) * HID + headOff + tx * 4;
        float4 o4;
        o4.x = (acc[i][0] + w2[0]) * invden;
        o4.y = (acc[i][1] + w2[1]) * invden;
        o4.z = (acc[i][2] + w2[2]) * invden;
        o4.w = (acc[i][3] + w2[3]) * invden;
        *reinterpret_cast<float4*>(op) = o4;
    }
}

// ---------------------------------------------------------------------------
extern "C" void kernel_launch(void* const* d_in, const int* in_sizes, int n_in,
                              void* d_out, int out_size)
{
    const float* query = (const float*)d_in[0];
    const float* key   = (const float*)d_in[1];
    const float* value = (const float*)d_in[2];
    const float* Wq = (const float*)d_in[3];
    const float* bq = (const float*)d_in[4];
    const float* Wk = (const float*)d_in[5];
    const float* bk = (const float*)d_in[6];
    const float* Wv = (const float*)d_in[7];
    const float* bv = (const float*)d_in[8];
    const float* Wo = (const float*)d_in[9];
    const float* bo = (const float*)d_in[10];
    const float* relk = (const float*)d_in[11];
    const float* relv = (const float*)d_in[12];
    float* out = (float*)d_out;

    const int ATTN_SMEM = (4 * 64 * PAD + 2 * 64 * NR + 64) * (int)sizeof(float);
    cudaFuncSetAttribute(attn_kernel, cudaFuncAttributeMaxDynamicSharedMemorySize,
                         ATTN_SMEM);

    dim3 ggrid(HID / 64, NROWS / 64);  // (16, 64)
    gemm_bias<<<ggrid, 256>>>(query, Wq, bq, nullptr, 0);  // -> g_Q
    gemm_bias<<<ggrid, 256>>>(key,   Wk, bk, nullptr, 1);  // -> g_K
    gemm_bias<<<ggrid, 256>>>(value, Wv, bv, nullptr, 2);  // -> g_V

    dim3 agrid(LSEQ / 64, NHEAD, BATCH);  // (32, 16, 2)
    attn_kernel<<<agrid, 256, ATTN_SMEM>>>(relk, relv);    // g_Q,g_K,g_V -> g_O

    gemm_bias<<<ggrid, 256>>>(nullptr, Wo, bo, out, 3);    // g_O -> out
}

// round 5
// speedup vs baseline: 1.0017x; 1.0017x over previous
#include <cuda_runtime.h>

#define LSEQ 2048
#define BATCH 2
#define HID 1024
#define NHEAD 16
#define DH 64
#define PREL 50
#define NR 101            // 2P+1
#define NROWS (LSEQ*BATCH)  // 4096
#define PAD 68

// Scratch (static device globals -- no runtime allocation)
__device__ float g_Q[NROWS * HID];
__device__ float g_K[NROWS * HID];
__device__ float g_V[NROWS * HID];
__device__ float g_O[NROWS * HID];

// ---------------------------------------------------------------------------
// GEMM: C[M,N] = A[M,K] * W[N,K]^T + bias[N]
// 64x64 block tile, 16-deep k panels, 4x4 register microtile, 256 threads.
// mode selects scratch src/dst so host never needs device symbol addresses:
//   mode 0: A=ext, C=g_Q ; 1: A=ext, C=g_K ; 2: A=ext, C=g_V ; 3: A=g_O, C=ext
// ---------------------------------------------------------------------------
__global__ __launch_bounds__(256) void gemm_bias(
    const float* __restrict__ A_ext, const float* __restrict__ W,
    const float* __restrict__ bias, float* __restrict__ C_ext, int mode)
{
    const float* A = (mode == 3) ? g_O : A_ext;
    float* C = (mode == 0) ? g_Q : (mode == 1) ? g_K : (mode == 2) ? g_V : C_ext;
    const int K = HID, N = HID;

    __shared__ float As[16][PAD];
    __shared__ float Ws[16][PAD];

    const int tid = threadIdx.x;
    const int tx = tid & 15, ty = tid >> 4;
    const int rowBase = blockIdx.y * 64;
    const int colBase = blockIdx.x * 64;
    const int lr = tid >> 2;          // 0..63
    const int lc = (tid & 3) * 4;     // 0,4,8,12
    const float* Aload = A + (size_t)(rowBase + lr) * K + lc;
    const float* Wload = W + (size_t)(colBase + lr) * K + lc;

    float acc[4][4] = {};

    for (int k0 = 0; k0 < K; k0 += 16) {
        float4 a4 = *reinterpret_cast<const float4*>(Aload + k0);
        float4 w4 = *reinterpret_cast<const float4*>(Wload + k0);
        As[lc + 0][lr] = a4.x; As[lc + 1][lr] = a4.y;
        As[lc + 2][lr] = a4.z; As[lc + 3][lr] = a4.w;
        Ws[lc + 0][lr] = w4.x; Ws[lc + 1][lr] = w4.y;
        Ws[lc + 2][lr] = w4.z; Ws[lc + 3][lr] = w4.w;
        __syncthreads();
        #pragma unroll
        for (int kk = 0; kk < 16; kk++) {
            float4 ra = *reinterpret_cast<const float4*>(&As[kk][ty * 4]);
            float4 rb = *reinterpret_cast<const float4*>(&Ws[kk][tx * 4]);
            float a[4] = {ra.x, ra.y, ra.z, ra.w};
            float w[4] = {rb.x, rb.y, rb.z, rb.w};
            #pragma unroll
            for (int i = 0; i < 4; i++)
                #pragma unroll
                for (int j = 0; j < 4; j++)
                    acc[i][j] += a[i] * w[j];
        }
        __syncthreads();
    }

    #pragma unroll
    for (int i = 0; i < 4; i++) {
        int row = rowBase + ty * 4 + i;
        #pragma unroll
        for (int j = 0; j < 4; j++) {
            int col = colBase + tx * 4 + j;
            C[(size_t)row * N + col] = acc[i][j] + bias[col];
        }
    }
}

// ---------------------------------------------------------------------------
// Fused relative-position attention.
// Grid: (q_tiles=32, heads=16, batch=2). Block: 256 threads, q-tile = 64.
// Streams K/V tiles of 64. Unnormalized streaming softmax (logits are tiny:
// ~N(0,0.41), no max subtraction needed).
//   S2[q][r]   = Q[q] . rel_k[r]                       (101 buckets)
//   logits     = (Q K^T + S2[q][clip(k-q)]) / 8
//   T[q][r]    = sum of p over k in bucket r  -> w2 = T @ rel_v
//   out        = (sum p*v + w2) / sum p
// ---------------------------------------------------------------------------
__global__ __launch_bounds__(256) void attn_kernel(
    const float* __restrict__ relk, const float* __restrict__ relv)
{
    extern __shared__ float sm[];
    float* QsT = sm;                    // [64 d][PAD] transposed
    float* KsT = QsT + 64 * PAD;        // [64 d][PAD] transposed
    float* Vs  = KsT + 64 * PAD;        // [64 k][PAD] row-major
    float* Ps  = Vs  + 64 * PAD;        // [64 q][PAD]
    float* S2  = Ps  + 64 * PAD;        // [64 q][NR]
    float* Tm  = S2  + 64 * NR;         // [64 q][NR]
    float* den = Tm  + 64 * NR;         // [64]

    const int tid = threadIdx.x;
    const int tx = tid & 15, ty = tid >> 4;
    const int qt = blockIdx.x, h = blockIdx.y, b = blockIdx.z;
    const int q0 = qt * 64;
    const int headOff = h * DH;

    // Load Q tile transposed: QsT[d][q]
    #pragma unroll
    for (int m = 0; m < 4; m++) {
        int idx = tid + m * 256;
        int row = idx >> 4;
        int c4 = (idx & 15) * 4;
        const float* gp = g_Q + ((size_t)(q0 + row) * BATCH + b) * HID + headOff + c4;
        float4 v = *reinterpret_cast<const float4*>(gp);
        QsT[(c4 + 0) * PAD + row] = v.x;
        QsT[(c4 + 1) * PAD + row] = v.y;
        QsT[(c4 + 2) * PAD + row] = v.z;
        QsT[(c4 + 3) * PAD + row] = v.w;
    }
    for (int o = tid; o < 64 * NR; o += 256) Tm[o] = 0.0f;
    if (tid < 64) den[tid] = 0.0f;
    __syncthreads();

    // S2[q][r] = sum_d Q[q][d] * rel_k[r][d]
    for (int o = tid; o < 64 * NR; o += 256) {
        int q = o / NR, r = o - q * NR;
        float s = 0.0f;
        #pragma unroll 16
        for (int d = 0; d < 64; d++)
            s += QsT[d * PAD + q] * __ldg(&relk[r * DH + d]);
        S2[o] = s;
    }

    float acc[4][4] = {};
    const float inv_scale = 0.125f;   // 1/sqrt(64)

    for (int kt = 0; kt < LSEQ / 64; kt++) {
        __syncthreads();  // protect K/V/Ps reuse across iterations (also covers S2 init)
        const int k0 = kt * 64;

        // Load K (transposed) and V (row-major) tiles
        #pragma unroll
        for (int m = 0; m < 4; m++) {
            int idx = tid + m * 256;
            int row = idx >> 4;
            int c4 = (idx & 15) * 4;
            const float* gk = g_K + ((size_t)(k0 + row) * BATCH + b) * HID + headOff + c4;
            float4 v = *reinterpret_cast<const float4*>(gk);
            KsT[(c4 + 0) * PAD + row] = v.x;
            KsT[(c4 + 1) * PAD + row] = v.y;
            KsT[(c4 + 2) * PAD + row] = v.z;
            KsT[(c4 + 3) * PAD + row] = v.w;
            const float* gv = g_V + ((size_t)(k0 + row) * BATCH + b) * HID + headOff + c4;
            *reinterpret_cast<float4*>(&Vs[row * PAD + c4]) =
                *reinterpret_cast<const float4*>(gv);
        }
        __syncthreads();

        // S = Q K^T  (4x4 microtile per thread)
        float s[4][4] = {};
        #pragma unroll 8
        for (int d = 0; d < 64; d++) {
            float4 ra = *reinterpret_cast<const float4*>(&QsT[d * PAD + ty * 4]);
            float4 rb = *reinterpret_cast<const float4*>(&KsT[d * PAD + tx * 4]);
            float a[4] = {ra.x, ra.y, ra.z, ra.w};
            float bb[4] = {rb.x, rb.y, rb.z, rb.w};
            #pragma unroll
            for (int i = 0; i < 4; i++)
                #pragma unroll
                for (int j = 0; j < 4; j++)
                    s[i][j] += a[i] * bb[j];
        }

        // Fast path: tile fully clipped (most tiles, since L >> P)
        int rel_const = -1;
        if (k0 - (q0 + 63) >= PREL)      rel_const = 2 * PREL;  // k - q >= P everywhere
        else if (q0 - (k0 + 63) >= PREL) rel_const = 0;         // q - k >= P everywhere

        #pragma unroll
        for (int i = 0; i < 4; i++) {
            const int ql = ty * 4 + i;
            const int qg = q0 + ql;
            float rowsum = 0.0f;
            if (rel_const >= 0) {
                const float s2v = S2[ql * NR + rel_const];
                #pragma unroll
                for (int j = 0; j < 4; j++) {
                    float p = __expf((s[i][j] + s2v) * inv_scale);
                    Ps[ql * PAD + tx * 4 + j] = p;
                    rowsum += p;
                }
                atomicAdd(&Tm[ql * NR + rel_const], rowsum);
            } else {
                #pragma unroll
                for (int j = 0; j < 4; j++) {
                    int kg = k0 + tx * 4 + j;
                    int rel = kg - qg;
                    rel = min(max(rel, -PREL), PREL) + PREL;
                    float p = __expf((s[i][j] + S2[ql * NR + rel]) * inv_scale);
                    Ps[ql * PAD + tx * 4 + j] = p;
                    rowsum += p;
                    atomicAdd(&Tm[ql * NR + rel], p);
                }
            }
            atomicAdd(&den[ql], rowsum);
        }
        __syncthreads();

        // O += P V
        #pragma unroll 8
        for (int k = 0; k < 64; k++) {
            float pa[4];
            #pragma unroll
            for (int i = 0; i < 4; i++) pa[i] = Ps[(ty * 4 + i) * PAD + k];
            float4 vb = *reinterpret_cast<const float4*>(&Vs[k * PAD + tx * 4]);
            float vv[4] = {vb.x, vb.y, vb.z, vb.w};
            #pragma unroll
            for (int i = 0; i < 4; i++)
                #pragma unroll
                for (int j = 0; j < 4; j++)
                    acc[i][j] += pa[i] * vv[j];
        }
    }
    __syncthreads();  // T, den complete

    // w2 = T @ rel_v ; normalize ; store per-head output
    #pragma unroll
    for (int i = 0; i < 4; i++) {
        const int ql = ty * 4 + i;
        float w2[4] = {0.f, 0.f, 0.f, 0.f};
        for (int r = 0; r < NR; r++) {
            float t = Tm[ql * NR + r];
            #pragma unroll
            for (int j = 0; j < 4; j++)
                w2[j] += t * __ldg(&relv[r * DH + tx * 4 + j]);
        }
        const float invden = 1.0f / den[ql];
        const int lg = q0 + ql;
        float* op = g_O + ((size_t)lg * BATCH + b) * HID + headOff + tx * 4;
        float4 o4;
        o4.x = (acc[i][0] + w2[0]) * invden;
        o4.y = (acc[i][1] + w2[1]) * invden;
        o4.z = (acc[i][2] + w2[2]) * invden;
        o4.w = (acc[i][3] + w2[3]) * invden;
        *reinterpret_cast<float4*>(op) = o4;
    }
}

// ---------------------------------------------------------------------------
extern "C" void kernel_launch(void* const* d_in, const int* in_sizes, int n_in,
                              void* d_out, int out_size)
{
    const float* query = (const float*)d_in[0];
    const float* key   = (const float*)d_in[1];
    const float* value = (const float*)d_in[2];
    const float* Wq = (const float*)d_in[3];
    const float* bq = (const float*)d_in[4];
    const float* Wk = (const float*)d_in[5];
    const float* bk = (const float*)d_in[6];
    const float* Wv = (const float*)d_in[7];
    const float* bv = (const float*)d_in[8];
    const float* Wo = (const float*)d_in[9];
    const float* bo = (const float*)d_in[10];
    const float* relk = (const float*)d_in[11];
    const float* relv = (const float*)d_in[12];
    float* out = (float*)d_out;

    const int ATTN_SMEM = (4 * 64 * PAD + 2 * 64 * NR + 64) * (int)sizeof(float);
    cudaFuncSetAttribute(attn_kernel, cudaFuncAttributeMaxDynamicSharedMemorySize,
                         ATTN_SMEM);

    dim3 ggrid(HID / 64, NROWS / 64);  // (16, 64)
    gemm_bias<<<ggrid, 256>>>(query, Wq, bq, nullptr, 0);  // -> g_Q
    gemm_bias<<<ggrid, 256>>>(key,   Wk, bk, nullptr, 1);  // -> g_K
    gemm_bias<<<ggrid, 256>>>(value, Wv, bv, nullptr, 2);  // -> g_V

    dim3 agrid(LSEQ / 64, NHEAD, BATCH);  // (32, 16, 2)
    attn_kernel<<<agrid, 256, ATTN_SMEM>>>(relk, relv);    // g_Q,g_K,g_V -> g_O

    gemm_bias<<<ggrid, 256>>>(nullptr, Wo, bo, out, 3);    // g_O -> out
}